// round 9
// baseline (speedup 1.0000x reference)
#include <cuda_runtime.h>
#include <cstdint>

#define T_LEN 4096
#define IN_DIM 256
#define H_DIM 1024
#define G4H   4096
#define NCTA  128
#define UNITS 8     // hidden units per CTA (128 * 8 = 1024); warp w owns unit w
#define NREP  4     // publish-buffer replicas (slice de-amplification)

// ---------------- device scratch (static: no allocations allowed) ----------
__device__ float g_xz[(size_t)T_LEN * G4H];     // 64 MB: input projections
__device__ float g_hall[(size_t)T_LEN * H_DIM]; // 16 MB: h outputs of current layer
// Fused data+flag publish buffers, replicated NREP x to spread L2-slice load:
// entry = {tag : hi32, h_bits : lo32}, single 8B relaxed store per entry.
// Tag = layer*(T_LEN+1) + t + 1 for step t; layer*(T_LEN+1) for h_{-1}.
// Equality-checked; replay-safe (stale tags from other layers/replays never
// equal the expected tag; zero-init == layer-0 h_{-1} with value 0).
__device__ unsigned long long g_pub[2][NREP][H_DIM];

// ---------------- memory-order helpers --------------------------------------
__device__ __forceinline__ unsigned long long ld_relaxed64(const unsigned long long* p) {
    unsigned long long v;
    asm volatile("ld.relaxed.gpu.global.b64 %0, [%1];" : "=l"(v) : "l"(p) : "memory");
    return v;
}
__device__ __forceinline__ void st_relaxed64(unsigned long long* p, unsigned long long v) {
    asm volatile("st.relaxed.gpu.global.b64 [%0], %1;" :: "l"(p), "l"(v) : "memory");
}

// ---------------- packed f32x2 FMA helper ----------------------------------
union F2u { float2 f; unsigned long long u; };

__device__ __forceinline__ void fma2(unsigned long long& d,
                                     unsigned long long a,
                                     unsigned long long b) {
    asm volatile("fma.rn.f32x2 %0, %1, %2, %0;" : "+l"(d) : "l"(a), "l"(b));
}

// ---------------- fast, overflow-safe activations ---------------------------
__device__ __forceinline__ float fast_sigmoid(float x) {
    return __fdividef(1.f, 1.f + __expf(-x));
}
__device__ __forceinline__ float fast_tanh(float x) {
    float a = fabsf(x);
    float e = __expf(-2.f * a);               // in (0, 1], never overflows
    float t = (1.f - e) * __fdividef(1.f, 1.f + e);
    return copysignf(t, x);
}

// ---------------- GEMM: xz = A @ W^T + bias --------------------------------
template<int K>
__global__ __launch_bounds__(256, 2)
void gemm_xz(const float* __restrict__ A_in,
             const float* __restrict__ W,
             const float* __restrict__ bias) {
    const float* A = A_in ? A_in : g_hall;   // nullptr => previous layer's h

    __shared__ float As[16][132];
    __shared__ float Bs[16][132];

    const int tid  = threadIdx.x;
    const int row0 = blockIdx.y * 128;
    const int col0 = blockIdx.x * 128;
    const int ty   = tid >> 4;
    const int tx   = tid & 15;

    float acc[8][8];
#pragma unroll
    for (int i = 0; i < 8; i++)
#pragma unroll
        for (int j = 0; j < 8; j++) acc[i][j] = 0.f;

    for (int k0 = 0; k0 < K; k0 += 16) {
#pragma unroll
        for (int i = 0; i < 2; i++) {
            int f  = tid + i * 256;
            int r  = f >> 2;
            int c4 = f & 3;
            float4 va = *(const float4*)(A + (size_t)(row0 + r) * K + k0 + c4 * 4);
            As[c4 * 4 + 0][r] = va.x;
            As[c4 * 4 + 1][r] = va.y;
            As[c4 * 4 + 2][r] = va.z;
            As[c4 * 4 + 3][r] = va.w;
            float4 vb = *(const float4*)(W + (size_t)(col0 + r) * K + k0 + c4 * 4);
            Bs[c4 * 4 + 0][r] = vb.x;
            Bs[c4 * 4 + 1][r] = vb.y;
            Bs[c4 * 4 + 2][r] = vb.z;
            Bs[c4 * 4 + 3][r] = vb.w;
        }
        __syncthreads();

#pragma unroll
        for (int k = 0; k < 16; k++) {
            float4 a0 = *(const float4*)&As[k][ty * 8];
            float4 a1 = *(const float4*)&As[k][ty * 8 + 4];
            float4 b0 = *(const float4*)&Bs[k][tx * 8];
            float4 b1 = *(const float4*)&Bs[k][tx * 8 + 4];
            float a[8] = {a0.x, a0.y, a0.z, a0.w, a1.x, a1.y, a1.z, a1.w};
            float b[8] = {b0.x, b0.y, b0.z, b0.w, b1.x, b1.y, b1.z, b1.w};
#pragma unroll
            for (int i = 0; i < 8; i++)
#pragma unroll
                for (int j = 0; j < 8; j++) acc[i][j] += a[i] * b[j];
        }
        __syncthreads();
    }

    float bj[8];
#pragma unroll
    for (int j = 0; j < 8; j++) bj[j] = bias[col0 + tx * 8 + j];

#pragma unroll
    for (int i = 0; i < 8; i++) {
        int r = row0 + ty * 8 + i;
#pragma unroll
        for (int j = 0; j < 8; j++) {
            g_xz[(size_t)r * G4H + col0 + tx * 8 + j] = acc[i][j] + bj[j];
        }
    }
}

// ---------------- recurrent scan -------------------------------------------
// 128 CTAs x 256 threads, all co-resident. CTA b owns hidden units [8b, 8b+8).
// NEW mapping: warp w owns ALL FOUR GATES of unit (8b + w): rows
// {g*H + 8b + w : g=0..3}. After its own shfl reductions, lane 0 of warp w
// has all four pre-activations -> computes gates and publishes its unit
// IMMEDIATELY. No sh_z, no second barrier, no 8-thread gate bottleneck.
// sh_h is double-buffered (parity t&1) so exactly ONE __syncthreads per step:
//   any thread past BAR@t+1 has finished dot@t, so a stage@t+2 into the same
//   parity buffer cannot race a dot@t reader.
__global__ __launch_bounds__(256, 1)
void lstm_scan(const float* __restrict__ Whh, int layer) {
    __shared__ float sh_h[2][H_DIM];   // double-buffered h broadcast stage

    const int bid   = blockIdx.x;
    const int tid   = threadIdx.x;
    const int wid   = tid >> 5;        // warp w -> unit ubase + w
    const int lane  = tid & 31;
    const int ubase = bid * UNITS;
    const int rep   = bid & (NREP - 1);
    const int unit  = ubase + wid;

    // W_hh rows for this warp: gate g of unit `unit`; lane covers cols
    // c*128 + lane*4 .. +3 for c = 0..7. 128 floats/thread in registers.
    float4 wreg[4][8];
#pragma unroll
    for (int g = 0; g < 4; g++) {
        const float4* wr =
            (const float4*)(Whh + ((size_t)g * H_DIM + unit) * H_DIM);
#pragma unroll
        for (int c = 0; c < 8; c++) wreg[g][c] = wr[c * 32 + lane];
    }

    const unsigned tagbase = (unsigned)layer * (unsigned)(T_LEN + 1);
    float c_state = 0.f;   // meaningful on lane 0 of each warp

    // publish h_{-1} = 0 with tag = tagbase into the parity-1 buffers
    if (tid < UNITS) {
        unsigned long long pk = (unsigned long long)tagbase << 32;
#pragma unroll
        for (int r = 0; r < NREP; r++)
            st_relaxed64(&g_pub[1][r][ubase + tid], pk);
    }

    for (int t = 0; t < T_LEN; t++) {
        // prefetch xz for this warp's unit (lane 0; independent of h)
        float xzi = 0.f, xzf = 0.f, xzg = 0.f, xzo = 0.f;
        if (lane == 0) {
            const float* xz = g_xz + (size_t)t * G4H + unit;
            xzi = __ldg(xz);
            xzf = __ldg(xz + H_DIM);
            xzg = __ldg(xz + 2 * H_DIM);
            xzo = __ldg(xz + 3 * H_DIM);
        }

        // wait for h_{t-1}: thread tid watches 4 fused slots of OUR replica.
        // Software-pipelined polling: one batch in flight while checking the
        // previous -> re-check period ~ half an L2 round trip.
        const int par = t & 1;
        {
            unsigned long long* buf = g_pub[par ^ 1][rep];
            const unsigned exp_tag  = tagbase + (unsigned)t;   // tag of h_{t-1}
            unsigned long long a0, a1, a2, a3;
            a0 = ld_relaxed64(buf + 4 * tid + 0);
            a1 = ld_relaxed64(buf + 4 * tid + 1);
            a2 = ld_relaxed64(buf + 4 * tid + 2);
            a3 = ld_relaxed64(buf + 4 * tid + 3);
            int tries = 0;
            for (;;) {
                // issue next batch before checking current one
                unsigned long long b0 = ld_relaxed64(buf + 4 * tid + 0);
                unsigned long long b1 = ld_relaxed64(buf + 4 * tid + 1);
                unsigned long long b2 = ld_relaxed64(buf + 4 * tid + 2);
                unsigned long long b3 = ld_relaxed64(buf + 4 * tid + 3);
                bool ok = ((unsigned)(a0 >> 32) == exp_tag) &
                          ((unsigned)(a1 >> 32) == exp_tag) &
                          ((unsigned)(a2 >> 32) == exp_tag) &
                          ((unsigned)(a3 >> 32) == exp_tag);
                if (ok) break;
                a0 = b0; a1 = b1; a2 = b2; a3 = b3;
                if (++tries > 6) __nanosleep(32);   // light backoff on long waits
            }
            // stage own 4 h values into this step's parity buffer
            ((float4*)sh_h[par])[tid] =
                make_float4(__uint_as_float((unsigned)a0),
                            __uint_as_float((unsigned)a1),
                            __uint_as_float((unsigned)a2),
                            __uint_as_float((unsigned)a3));
        }
        __syncthreads();   // the ONLY barrier per step

        // packed dot products: 4 gate-rows of our unit, 32 cols per lane
        unsigned long long acc[4];
        {
            F2u z; z.f = make_float2(0.f, 0.f);
            acc[0] = acc[1] = acc[2] = acc[3] = z.u;
        }
        const float4* hbuf = (const float4*)sh_h[par];
#pragma unroll
        for (int c = 0; c < 8; c++) {
            float4 hv = hbuf[c * 32 + lane];
            F2u hlo, hhi;
            hlo.f = make_float2(hv.x, hv.y);
            hhi.f = make_float2(hv.z, hv.w);
#pragma unroll
            for (int g = 0; g < 4; g++) {
                F2u wlo, whi;
                wlo.f = make_float2(wreg[g][c].x, wreg[g][c].y);
                whi.f = make_float2(wreg[g][c].z, wreg[g][c].w);
                fma2(acc[g], wlo.u, hlo.u);
                fma2(acc[g], whi.u, hhi.u);
            }
        }

        // 4 independent butterfly reductions, interleaved to pipeline
        float s0, s1, s2, s3;
        {
            F2u a0, a1, a2, a3;
            a0.u = acc[0]; a1.u = acc[1]; a2.u = acc[2]; a3.u = acc[3];
            s0 = a0.f.x + a0.f.y;
            s1 = a1.f.x + a1.f.y;
            s2 = a2.f.x + a2.f.y;
            s3 = a3.f.x + a3.f.y;
#pragma unroll
            for (int off = 16; off; off >>= 1) {
                s0 += __shfl_xor_sync(0xffffffffu, s0, off);
                s1 += __shfl_xor_sync(0xffffffffu, s1, off);
                s2 += __shfl_xor_sync(0xffffffffu, s2, off);
                s3 += __shfl_xor_sync(0xffffffffu, s3, off);
            }
        }

        // gates + immediate per-warp publish (lane 0); no CTA barrier needed
        if (lane == 0) {
            float zi = s0 + xzi;
            float zf = s1 + xzf;
            float zg = s2 + xzg;
            float zo = s3 + xzo;
            float ig = fast_sigmoid(zi);
            float fg = fast_sigmoid(zf);
            float gg = fast_tanh(zg);
            float og = fast_sigmoid(zo);
            c_state  = fg * c_state + ig * gg;
            float h  = og * fast_tanh(c_state);
            unsigned long long pk =
                ((unsigned long long)(tagbase + (unsigned)t + 1u) << 32) |
                (unsigned long long)__float_as_uint(h);
            unsigned long long* dst = &g_pub[par][0][unit];
#pragma unroll
            for (int r = 0; r < NREP; r++)
                st_relaxed64(dst + (size_t)r * H_DIM, pk); // fused publish x4
            g_hall[(size_t)t * H_DIM + unit] = h;          // consumed next launch
        }
    }
}

// ---------------- final FC: out[t][o] = hall[t] . fcW[o] + fcb[o] ----------
__global__ void fc_kernel(const float* __restrict__ W,
                          const float* __restrict__ b,
                          float* __restrict__ out) {
    int t    = blockIdx.x;
    int o    = threadIdx.x >> 5;   // 10 warps
    int lane = threadIdx.x & 31;
    const float4* h = (const float4*)(g_hall + (size_t)t * H_DIM);
    const float4* w = (const float4*)(W + (size_t)o * H_DIM);
    float s = 0.f;
#pragma unroll
    for (int c = 0; c < 8; c++) {
        float4 hv = h[c * 32 + lane];
        float4 wv = w[c * 32 + lane];
        s += hv.x * wv.x + hv.y * wv.y + hv.z * wv.z + hv.w * wv.w;
    }
#pragma unroll
    for (int off = 16; off; off >>= 1)
        s += __shfl_xor_sync(0xffffffffu, s, off);
    if (lane == 0) out[t * 10 + o] = s + b[o];
}

// ---------------- launch ----------------------------------------------------
extern "C" void kernel_launch(void* const* d_in, const int* in_sizes, int n_in,
                              void* d_out, int out_size) {
    const float* x     = (const float*)d_in[0];
    const float* Wih0  = (const float*)d_in[1];
    const float* Whh0  = (const float*)d_in[2];
    const float* b0    = (const float*)d_in[3];
    const float* WihR  = (const float*)d_in[4];
    const float* WhhR  = (const float*)d_in[5];
    const float* bR    = (const float*)d_in[6];
    const float* fcW   = (const float*)d_in[7];
    const float* fcb   = (const float*)d_in[8];
    float*       out   = (float*)d_out;

    dim3 ggrid(G4H / 128, T_LEN / 128);
    dim3 gblk(256);

    // layer 0
    gemm_xz<IN_DIM><<<ggrid, gblk>>>(x, Wih0, b0);
    lstm_scan<<<NCTA, 256>>>(Whh0, 0);

    // layers 1..3
    for (int l = 1; l < 4; l++) {
        const float* Wih = WihR + (size_t)(l - 1) * G4H * H_DIM;
        const float* Whh = WhhR + (size_t)(l - 1) * G4H * H_DIM;
        const float* bb  = bR   + (size_t)(l - 1) * G4H;
        gemm_xz<H_DIM><<<ggrid, gblk>>>(nullptr /* = g_hall */, Wih, bb);
        lstm_scan<<<NCTA, 256>>>(Whh, l);
    }

    fc_kernel<<<T_LEN, 320>>>(fcW, fcb, out);
}

// round 10
// speedup vs baseline: 1.0211x; 1.0211x over previous
#include <cuda_runtime.h>
#include <cstdint>

#define T_LEN 4096
#define IN_DIM 256
#define H_DIM 1024
#define G4H   4096
#define NCTA  128
#define UNITS 8     // hidden units per CTA (128 * 8 = 1024)
#define NREP  4     // publish-buffer replicas (slice de-amplification)

// ---------------- device scratch (static: no allocations allowed) ----------
__device__ float g_xz[(size_t)T_LEN * G4H];     // 64 MB: input projections
__device__ float g_hall[(size_t)T_LEN * H_DIM]; // 16 MB: h outputs of current layer
// Fused data+flag publish buffers, replicated NREP x to spread L2-slice load:
// entry = {tag : hi32, h_bits : lo32}, single 8B relaxed store per entry.
// Tag = layer*(T_LEN+1) + t + 1 for step t; layer*(T_LEN+1) for h_{-1}.
// Equality-checked; replay-safe (stale tags from other layers/replays never
// equal the expected tag; zero-init == layer-0 h_{-1} with value 0).
__device__ unsigned long long g_pub[2][NREP][H_DIM];
// Compact HINT tags: one u32 per producer CTA per replica. Advisory only --
// correctness rests on the fused per-slot tags above. Polling this 512B
// region instead of the 8KB data region cuts failed-poll L2 traffic ~16x.
__device__ unsigned g_ctag[2][NREP][NCTA];

// ---------------- memory-order helpers --------------------------------------
__device__ __forceinline__ unsigned long long ld_relaxed64(const unsigned long long* p) {
    unsigned long long v;
    asm volatile("ld.relaxed.gpu.global.b64 %0, [%1];" : "=l"(v) : "l"(p) : "memory");
    return v;
}
__device__ __forceinline__ void st_relaxed64(unsigned long long* p, unsigned long long v) {
    asm volatile("st.relaxed.gpu.global.b64 [%0], %1;" :: "l"(p), "l"(v) : "memory");
}
__device__ __forceinline__ unsigned ld_relaxed32(const unsigned* p) {
    unsigned v;
    asm volatile("ld.relaxed.gpu.global.u32 %0, [%1];" : "=r"(v) : "l"(p) : "memory");
    return v;
}
__device__ __forceinline__ void st_relaxed32(unsigned* p, unsigned v) {
    asm volatile("st.relaxed.gpu.global.u32 [%0], %1;" :: "l"(p), "r"(v) : "memory");
}

// ---------------- packed f32x2 FMA helper ----------------------------------
union F2u { float2 f; unsigned long long u; };

__device__ __forceinline__ void fma2(unsigned long long& d,
                                     unsigned long long a,
                                     unsigned long long b) {
    asm volatile("fma.rn.f32x2 %0, %1, %2, %0;" : "+l"(d) : "l"(a), "l"(b));
}

// ---------------- fast, overflow-safe activations ---------------------------
__device__ __forceinline__ float fast_sigmoid(float x) {
    return __fdividef(1.f, 1.f + __expf(-x));
}
__device__ __forceinline__ float fast_tanh(float x) {
    float a = fabsf(x);
    float e = __expf(-2.f * a);               // in (0, 1], never overflows
    float t = (1.f - e) * __fdividef(1.f, 1.f + e);
    return copysignf(t, x);
}

// ---------------- GEMM: xz = A @ W^T + bias --------------------------------
template<int K>
__global__ __launch_bounds__(256, 2)
void gemm_xz(const float* __restrict__ A_in,
             const float* __restrict__ W,
             const float* __restrict__ bias) {
    const float* A = A_in ? A_in : g_hall;   // nullptr => previous layer's h

    __shared__ float As[16][132];
    __shared__ float Bs[16][132];

    const int tid  = threadIdx.x;
    const int row0 = blockIdx.y * 128;
    const int col0 = blockIdx.x * 128;
    const int ty   = tid >> 4;
    const int tx   = tid & 15;

    float acc[8][8];
#pragma unroll
    for (int i = 0; i < 8; i++)
#pragma unroll
        for (int j = 0; j < 8; j++) acc[i][j] = 0.f;

    for (int k0 = 0; k0 < K; k0 += 16) {
#pragma unroll
        for (int i = 0; i < 2; i++) {
            int f  = tid + i * 256;
            int r  = f >> 2;
            int c4 = f & 3;
            float4 va = *(const float4*)(A + (size_t)(row0 + r) * K + k0 + c4 * 4);
            As[c4 * 4 + 0][r] = va.x;
            As[c4 * 4 + 1][r] = va.y;
            As[c4 * 4 + 2][r] = va.z;
            As[c4 * 4 + 3][r] = va.w;
            float4 vb = *(const float4*)(W + (size_t)(col0 + r) * K + k0 + c4 * 4);
            Bs[c4 * 4 + 0][r] = vb.x;
            Bs[c4 * 4 + 1][r] = vb.y;
            Bs[c4 * 4 + 2][r] = vb.z;
            Bs[c4 * 4 + 3][r] = vb.w;
        }
        __syncthreads();

#pragma unroll
        for (int k = 0; k < 16; k++) {
            float4 a0 = *(const float4*)&As[k][ty * 8];
            float4 a1 = *(const float4*)&As[k][ty * 8 + 4];
            float4 b0 = *(const float4*)&Bs[k][tx * 8];
            float4 b1 = *(const float4*)&Bs[k][tx * 8 + 4];
            float a[8] = {a0.x, a0.y, a0.z, a0.w, a1.x, a1.y, a1.z, a1.w};
            float b[8] = {b0.x, b0.y, b0.z, b0.w, b1.x, b1.y, b1.z, b1.w};
#pragma unroll
            for (int i = 0; i < 8; i++)
#pragma unroll
                for (int j = 0; j < 8; j++) acc[i][j] += a[i] * b[j];
        }
        __syncthreads();
    }

    float bj[8];
#pragma unroll
    for (int j = 0; j < 8; j++) bj[j] = bias[col0 + tx * 8 + j];

#pragma unroll
    for (int i = 0; i < 8; i++) {
        int r = row0 + ty * 8 + i;
#pragma unroll
        for (int j = 0; j < 8; j++) {
            g_xz[(size_t)r * G4H + col0 + tx * 8 + j] = acc[i][j] + bj[j];
        }
    }
}

// ---------------- recurrent scan (R8 skeleton + hint tags) ------------------
// 128 CTAs x 256 threads, all co-resident. CTA b owns hidden units [8b, 8b+8).
// W_hh slice (32 rows x 1024) lives in REGISTERS (128 floats/thread).
// Publish (warp 0, lanes 0..7): ONE coalesced fused-store wave per replica
// (64B), then lane 0 writes the compact hint tag per replica.
// Consume: spin on 512B hint region (8 lines), then single verified read of
// the 8KB fused data.
__global__ __launch_bounds__(256, 1)
void lstm_scan(const float* __restrict__ Whh, int layer) {
    __shared__ float sh_h[H_DIM];
    __shared__ float sh_z[32];

    const int bid   = blockIdx.x;
    const int tid   = threadIdx.x;
    const int wid   = tid >> 5;
    const int lane  = tid & 31;
    const int ubase = bid * UNITS;
    const int rep   = bid & (NREP - 1);

    // load this CTA's W_hh slice into registers.
    // warp w handles slice-rows s = 4w..4w+3, s -> (gate = s>>3, unit = s&7).
    float4 wreg[4][8];
#pragma unroll
    for (int j = 0; j < 4; j++) {
        int s    = wid * 4 + j;
        int gate = s >> 3;
        int unit = s & 7;
        const float4* wr =
            (const float4*)(Whh + ((size_t)gate * H_DIM + ubase + unit) * H_DIM);
#pragma unroll
        for (int c = 0; c < 8; c++) wreg[j][c] = wr[c * 32 + lane];
    }

    const unsigned tagbase = (unsigned)layer * (unsigned)(T_LEN + 1);
    float c_state = 0.f;   // meaningful for tid < 8 only

    // publish h_{-1} = 0 with tag = tagbase into the parity-1 buffers
    if (tid < UNITS) {
        unsigned long long pk = (unsigned long long)tagbase << 32;
#pragma unroll
        for (int r = 0; r < NREP; r++)
            st_relaxed64(&g_pub[1][r][ubase + tid], pk);
        if (tid == 0) {
#pragma unroll
            for (int r = 0; r < NREP; r++)
                st_relaxed32(&g_ctag[1][r][bid], tagbase);
        }
    }

    for (int t = 0; t < T_LEN; t++) {
        // prefetch xz for this step (independent of h; overlaps the wait)
        float xzi = 0.f, xzf = 0.f, xzg = 0.f, xzo = 0.f;
        if (tid < UNITS) {
            const float* xz = g_xz + (size_t)t * G4H + ubase + tid;
            xzi = __ldg(xz);
            xzf = __ldg(xz + H_DIM);
            xzg = __ldg(xz + 2 * H_DIM);
            xzo = __ldg(xz + 3 * H_DIM);
        }

        const int par = (t + 1) & 1;                      // parity of h_{t-1}
        const unsigned exp_tag = tagbase + (unsigned)t;   // tag of h_{t-1}

        // Phase 1: spin on the COMPACT hint tag of our producer (CTA tid/2);
        // thread tid's fused slots 4tid..4tid+3 belong to producer CTA tid/2.
        // 512B region per replica -> 8 lines per poll round (16x less than 8KB).
        {
            const unsigned* ct = &g_ctag[par][rep][tid >> 1];
            int tries = 0;
            while (ld_relaxed32(ct) != exp_tag) {
                if (++tries > 2) __nanosleep(40);
            }
        }

        // Phase 2: single verified read of own 4 fused slots (hint says ready;
        // embedded tags are the ground truth -- retry in the rare visibility gap).
        {
            unsigned long long* buf = g_pub[par][rep];
            unsigned long long pr0, pr1, pr2, pr3;
            for (;;) {
                pr0 = ld_relaxed64(buf + 4 * tid + 0);
                pr1 = ld_relaxed64(buf + 4 * tid + 1);
                pr2 = ld_relaxed64(buf + 4 * tid + 2);
                pr3 = ld_relaxed64(buf + 4 * tid + 3);
                bool ok = ((unsigned)(pr0 >> 32) == exp_tag) &
                          ((unsigned)(pr1 >> 32) == exp_tag) &
                          ((unsigned)(pr2 >> 32) == exp_tag) &
                          ((unsigned)(pr3 >> 32) == exp_tag);
                if (ok) break;
            }
            ((float4*)sh_h)[tid] =
                make_float4(__uint_as_float((unsigned)pr0),
                            __uint_as_float((unsigned)pr1),
                            __uint_as_float((unsigned)pr2),
                            __uint_as_float((unsigned)pr3));
        }
        __syncthreads();                                   // (B)

        // packed dot products: 4 rows per warp, 32 cols per lane (conflict-free)
        unsigned long long acc[4];
        {
            F2u z; z.f = make_float2(0.f, 0.f);
            acc[0] = acc[1] = acc[2] = acc[3] = z.u;
        }
#pragma unroll
        for (int c = 0; c < 8; c++) {
            float4 hv = ((const float4*)sh_h)[c * 32 + lane];
            F2u hlo, hhi;
            hlo.f = make_float2(hv.x, hv.y);
            hhi.f = make_float2(hv.z, hv.w);
#pragma unroll
            for (int j = 0; j < 4; j++) {
                F2u wlo, whi;
                wlo.f = make_float2(wreg[j][c].x, wreg[j][c].y);
                whi.f = make_float2(wreg[j][c].z, wreg[j][c].w);
                fma2(acc[j], wlo.u, hlo.u);
                fma2(acc[j], whi.u, hhi.u);
            }
        }

        // 4 independent butterfly reductions, interleaved to pipeline
        float s0, s1, s2, s3;
        {
            F2u a0, a1, a2, a3;
            a0.u = acc[0]; a1.u = acc[1]; a2.u = acc[2]; a3.u = acc[3];
            s0 = a0.f.x + a0.f.y;
            s1 = a1.f.x + a1.f.y;
            s2 = a2.f.x + a2.f.y;
            s3 = a3.f.x + a3.f.y;
#pragma unroll
            for (int off = 16; off; off >>= 1) {
                s0 += __shfl_xor_sync(0xffffffffu, s0, off);
                s1 += __shfl_xor_sync(0xffffffffu, s1, off);
                s2 += __shfl_xor_sync(0xffffffffu, s2, off);
                s3 += __shfl_xor_sync(0xffffffffu, s3, off);
            }
        }
        if (lane == 0) {
            sh_z[wid * 4 + 0] = s0;
            sh_z[wid * 4 + 1] = s1;
            sh_z[wid * 4 + 2] = s2;
            sh_z[wid * 4 + 3] = s3;
        }
        __syncthreads();                                   // (C)

        // gates on threads 0..7; sh_z[u]=i, [8+u]=f, [16+u]=g, [24+u]=o
        if (tid < UNITS) {
            float zi = sh_z[tid]      + xzi;
            float zf = sh_z[8 + tid]  + xzf;
            float zg = sh_z[16 + tid] + xzg;
            float zo = sh_z[24 + tid] + xzo;
            float ig = fast_sigmoid(zi);
            float fg = fast_sigmoid(zf);
            float gg = fast_tanh(zg);
            float og = fast_sigmoid(zo);
            c_state  = fg * c_state + ig * gg;
            float h  = og * fast_tanh(c_state);
            unsigned long long pk =
                ((unsigned long long)(exp_tag + 1u) << 32) |
                (unsigned long long)__float_as_uint(h);
            unsigned long long* dst = &g_pub[t & 1][0][ubase + tid];
#pragma unroll
            for (int r = 0; r < NREP; r++)
                st_relaxed64(dst + (size_t)r * H_DIM, pk); // coalesced 64B/replica
            if (tid == 0) {                                // hint after data
#pragma unroll
                for (int r = 0; r < NREP; r++)
                    st_relaxed32(&g_ctag[t & 1][r][bid], exp_tag + 1u);
            }
            g_hall[(size_t)t * H_DIM + ubase + tid] = h;   // consumed next launch
        }
        // smem hazards: identical to R8 -- sh_h overwrite at t+1 is behind each
        // thread's own phase-2 (post-(C)@t for that thread), sh_z overwrite
        // behind (B)@t+1. 2 barriers/step.
    }
}

// ---------------- final FC: out[t][o] = hall[t] . fcW[o] + fcb[o] ----------
__global__ void fc_kernel(const float* __restrict__ W,
                          const float* __restrict__ b,
                          float* __restrict__ out) {
    int t    = blockIdx.x;
    int o    = threadIdx.x >> 5;   // 10 warps
    int lane = threadIdx.x & 31;
    const float4* h = (const float4*)(g_hall + (size_t)t * H_DIM);
    const float4* w = (const float4*)(W + (size_t)o * H_DIM);
    float s = 0.f;
#pragma unroll
    for (int c = 0; c < 8; c++) {
        float4 hv = h[c * 32 + lane];
        float4 wv = w[c * 32 + lane];
        s += hv.x * wv.x + hv.y * wv.y + hv.z * wv.z + hv.w * wv.w;
    }
#pragma unroll
    for (int off = 16; off; off >>= 1)
        s += __shfl_xor_sync(0xffffffffu, s, off);
    if (lane == 0) out[t * 10 + o] = s + b[o];
}

// ---------------- launch ----------------------------------------------------
extern "C" void kernel_launch(void* const* d_in, const int* in_sizes, int n_in,
                              void* d_out, int out_size) {
    const float* x     = (const float*)d_in[0];
    const float* Wih0  = (const float*)d_in[1];
    const float* Whh0  = (const float*)d_in[2];
    const float* b0    = (const float*)d_in[3];
    const float* WihR  = (const float*)d_in[4];
    const float* WhhR  = (const float*)d_in[5];
    const float* bR    = (const float*)d_in[6];
    const float* fcW   = (const float*)d_in[7];
    const float* fcb   = (const float*)d_in[8];
    float*       out   = (float*)d_out;

    dim3 ggrid(G4H / 128, T_LEN / 128);
    dim3 gblk(256);

    // layer 0
    gemm_xz<IN_DIM><<<ggrid, gblk>>>(x, Wih0, b0);
    lstm_scan<<<NCTA, 256>>>(Whh0, 0);

    // layers 1..3
    for (int l = 1; l < 4; l++) {
        const float* Wih = WihR + (size_t)(l - 1) * G4H * H_DIM;
        const float* Whh = WhhR + (size_t)(l - 1) * G4H * H_DIM;
        const float* bb  = bR   + (size_t)(l - 1) * G4H;
        gemm_xz<H_DIM><<<ggrid, gblk>>>(nullptr /* = g_hall */, Wih, bb);
        lstm_scan<<<NCTA, 256>>>(Whh, l);
    }

    fc_kernel<<<T_LEN, 320>>>(fcW, fcb, out);
}

// round 11
// speedup vs baseline: 2.7117x; 2.6555x over previous
#include <cuda_runtime.h>
#include <cstdint>

#define T_LEN 4096
#define IN_DIM 256
#define H_DIM 1024
#define G4H   4096
#define NCTA  128
#define UNITS 8     // hidden units per CTA (128 * 8 = 1024); warp w computes unit w
#define NREP  4     // publish-buffer replicas (slice de-amplification)

// ---------------- device scratch (static: no allocations allowed) ----------
__device__ float g_xz[(size_t)T_LEN * G4H];     // 64 MB: input projections
__device__ float g_hall[(size_t)T_LEN * H_DIM]; // 16 MB: h outputs of current layer
// Fused data+flag publish buffers, replicated NREP x to spread L2-slice load:
// entry = {tag : hi32, h_bits : lo32}, single 8B relaxed store per entry.
// Tag = layer*(T_LEN+1) + t + 1 for step t; layer*(T_LEN+1) for h_{-1}.
// Equality-checked; replay-safe (stale tags from other layers/replays never
// equal the expected tag; zero-init == layer-0 h_{-1} with value 0).
// 128-byte aligned so 16B vector polls are legal at 32B/thread offsets.
__device__ __align__(128) unsigned long long g_pub[2][NREP][H_DIM];

// ---------------- memory-order helpers --------------------------------------
__device__ __forceinline__ void st_relaxed64(unsigned long long* p, unsigned long long v) {
    asm volatile("st.relaxed.gpu.global.b64 [%0], %1;" :: "l"(p), "l"(v) : "memory");
}
// 16B volatile poll: two 8B elements, each naturally 8B-atomic (producers
// write each element with a single 8B store). Volatile => L2-fresh each time.
__device__ __forceinline__ void ld_vol_v2(const unsigned long long* p,
                                          unsigned long long& a,
                                          unsigned long long& b) {
    asm volatile("ld.volatile.global.v2.b64 {%0, %1}, [%2];"
                 : "=l"(a), "=l"(b) : "l"(p) : "memory");
}

// ---------------- packed f32x2 FMA helper ----------------------------------
union F2u { float2 f; unsigned long long u; };

__device__ __forceinline__ void fma2(unsigned long long& d,
                                     unsigned long long a,
                                     unsigned long long b) {
    asm volatile("fma.rn.f32x2 %0, %1, %2, %0;" : "+l"(d) : "l"(a), "l"(b));
}

// ---------------- fast, overflow-safe activations ---------------------------
__device__ __forceinline__ float fast_sigmoid(float x) {
    return __fdividef(1.f, 1.f + __expf(-x));
}
__device__ __forceinline__ float fast_tanh(float x) {
    float a = fabsf(x);
    float e = __expf(-2.f * a);               // in (0, 1], never overflows
    float t = (1.f - e) * __fdividef(1.f, 1.f + e);
    return copysignf(t, x);
}

// ---------------- GEMM: xz = A @ W^T + bias --------------------------------
template<int K>
__global__ __launch_bounds__(256, 2)
void gemm_xz(const float* __restrict__ A_in,
             const float* __restrict__ W,
             const float* __restrict__ bias) {
    const float* A = A_in ? A_in : g_hall;   // nullptr => previous layer's h

    __shared__ float As[16][132];
    __shared__ float Bs[16][132];

    const int tid  = threadIdx.x;
    const int row0 = blockIdx.y * 128;
    const int col0 = blockIdx.x * 128;
    const int ty   = tid >> 4;
    const int tx   = tid & 15;

    float acc[8][8];
#pragma unroll
    for (int i = 0; i < 8; i++)
#pragma unroll
        for (int j = 0; j < 8; j++) acc[i][j] = 0.f;

    for (int k0 = 0; k0 < K; k0 += 16) {
#pragma unroll
        for (int i = 0; i < 2; i++) {
            int f  = tid + i * 256;
            int r  = f >> 2;
            int c4 = f & 3;
            float4 va = *(const float4*)(A + (size_t)(row0 + r) * K + k0 + c4 * 4);
            As[c4 * 4 + 0][r] = va.x;
            As[c4 * 4 + 1][r] = va.y;
            As[c4 * 4 + 2][r] = va.z;
            As[c4 * 4 + 3][r] = va.w;
            float4 vb = *(const float4*)(W + (size_t)(col0 + r) * K + k0 + c4 * 4);
            Bs[c4 * 4 + 0][r] = vb.x;
            Bs[c4 * 4 + 1][r] = vb.y;
            Bs[c4 * 4 + 2][r] = vb.z;
            Bs[c4 * 4 + 3][r] = vb.w;
        }
        __syncthreads();

#pragma unroll
        for (int k = 0; k < 16; k++) {
            float4 a0 = *(const float4*)&As[k][ty * 8];
            float4 a1 = *(const float4*)&As[k][ty * 8 + 4];
            float4 b0 = *(const float4*)&Bs[k][tx * 8];
            float4 b1 = *(const float4*)&Bs[k][tx * 8 + 4];
            float a[8] = {a0.x, a0.y, a0.z, a0.w, a1.x, a1.y, a1.z, a1.w};
            float b[8] = {b0.x, b0.y, b0.z, b0.w, b1.x, b1.y, b1.z, b1.w};
#pragma unroll
            for (int i = 0; i < 8; i++)
#pragma unroll
                for (int j = 0; j < 8; j++) acc[i][j] += a[i] * b[j];
        }
        __syncthreads();
    }

    float bj[8];
#pragma unroll
    for (int j = 0; j < 8; j++) bj[j] = bias[col0 + tx * 8 + j];

#pragma unroll
    for (int i = 0; i < 8; i++) {
        int r = row0 + ty * 8 + i;
#pragma unroll
        for (int j = 0; j < 8; j++) {
            g_xz[(size_t)r * G4H + col0 + tx * 8 + j] = acc[i][j] + bj[j];
        }
    }
}

// ---------------- recurrent scan -------------------------------------------
// 128 CTAs x 256 threads, all co-resident. CTA b owns hidden units [8b, 8b+8).
// Warp w owns ALL 4 GATES of unit 8b+w (rows {g*H + 8b + w}); after its own
// shfl reduce, lane 0 computes the gates -> 8 units' gate chains run in
// PARALLEL across warps (R8 serialized them on 8 threads).
// Publish stays BATCHED: packed {tag,h} gathered in smem; after BAR(C),
// warp r (r<4) lane u stores unit u to replica r -> 4 parallel 64B waves.
// Poll: per-thread own 32B via 2 x 16B volatile vector loads, pipelined.
__global__ __launch_bounds__(256, 1)
void lstm_scan(const float* __restrict__ Whh, int layer) {
    __shared__ float sh_h[H_DIM];
    __shared__ unsigned long long sh_pk[UNITS];   // packed {tag,h} per unit

    const int bid   = blockIdx.x;
    const int tid   = threadIdx.x;
    const int wid   = tid >> 5;        // warp w -> unit ubase + w
    const int lane  = tid & 31;
    const int ubase = bid * UNITS;
    const int rep   = bid & (NREP - 1);
    const int unit  = ubase + wid;

    // W_hh rows for this warp: gate g of unit `unit`; lane covers cols
    // c*128 + lane*4 .. +3 for c = 0..7. 128 floats/thread in registers.
    float4 wreg[4][8];
#pragma unroll
    for (int g = 0; g < 4; g++) {
        const float4* wr =
            (const float4*)(Whh + ((size_t)g * H_DIM + unit) * H_DIM);
#pragma unroll
        for (int c = 0; c < 8; c++) wreg[g][c] = wr[c * 32 + lane];
    }

    const unsigned tagbase = (unsigned)layer * (unsigned)(T_LEN + 1);
    float c_state = 0.f;   // lane 0 of each warp carries its unit's cell state

    // publish h_{-1} = 0 with tag = tagbase into the parity-1 buffers
    // (warps 0..3 -> replica wid, lanes 0..7 -> units: 4 parallel 64B waves)
    if (wid < NREP && lane < UNITS) {
        st_relaxed64(&g_pub[1][wid][ubase + lane],
                     (unsigned long long)tagbase << 32);
    }

    for (int t = 0; t < T_LEN; t++) {
        // prefetch xz for this warp's unit (lane 0; independent of h)
        float xzi = 0.f, xzf = 0.f, xzg = 0.f, xzo = 0.f;
        if (lane == 0) {
            const float* xz = g_xz + (size_t)t * G4H + unit;
            xzi = __ldg(xz);
            xzf = __ldg(xz + H_DIM);
            xzg = __ldg(xz + 2 * H_DIM);
            xzo = __ldg(xz + 3 * H_DIM);
        }

        const int par = (t + 1) & 1;                      // parity of h_{t-1}
        const unsigned exp_tag = tagbase + (unsigned)t;   // tag of h_{t-1}

        // wait for h_{t-1}: thread tid owns 4 fused slots (32B) of OUR replica;
        // 2 x 16B volatile loads, software-pipelined; stops loading once tagged.
        {
            const unsigned long long* buf = &g_pub[par][rep][4 * tid];
            unsigned long long a0, a1, a2, a3;
            ld_vol_v2(buf + 0, a0, a1);
            ld_vol_v2(buf + 2, a2, a3);
            int tries = 0;
            for (;;) {
                unsigned long long b0, b1, b2, b3;
                ld_vol_v2(buf + 0, b0, b1);       // next batch in flight
                ld_vol_v2(buf + 2, b2, b3);
                bool ok = ((unsigned)(a0 >> 32) == exp_tag) &
                          ((unsigned)(a1 >> 32) == exp_tag) &
                          ((unsigned)(a2 >> 32) == exp_tag) &
                          ((unsigned)(a3 >> 32) == exp_tag);
                if (ok) break;
                a0 = b0; a1 = b1; a2 = b2; a3 = b3;
                if (++tries > 4) __nanosleep(32);
            }
            ((float4*)sh_h)[tid] =
                make_float4(__uint_as_float((unsigned)a0),
                            __uint_as_float((unsigned)a1),
                            __uint_as_float((unsigned)a2),
                            __uint_as_float((unsigned)a3));
        }
        __syncthreads();                                   // (B)

        // packed dot products: 4 gate-rows of our unit, 32 cols per lane
        unsigned long long acc[4];
        {
            F2u z; z.f = make_float2(0.f, 0.f);
            acc[0] = acc[1] = acc[2] = acc[3] = z.u;
        }
#pragma unroll
        for (int c = 0; c < 8; c++) {
            float4 hv = ((const float4*)sh_h)[c * 32 + lane];
            F2u hlo, hhi;
            hlo.f = make_float2(hv.x, hv.y);
            hhi.f = make_float2(hv.z, hv.w);
#pragma unroll
            for (int g = 0; g < 4; g++) {
                F2u wlo, whi;
                wlo.f = make_float2(wreg[g][c].x, wreg[g][c].y);
                whi.f = make_float2(wreg[g][c].z, wreg[g][c].w);
                fma2(acc[g], wlo.u, hlo.u);
                fma2(acc[g], whi.u, hhi.u);
            }
        }

        // 4 independent butterfly reductions, interleaved to pipeline
        float s0, s1, s2, s3;
        {
            F2u a0, a1, a2, a3;
            a0.u = acc[0]; a1.u = acc[1]; a2.u = acc[2]; a3.u = acc[3];
            s0 = a0.f.x + a0.f.y;
            s1 = a1.f.x + a1.f.y;
            s2 = a2.f.x + a2.f.y;
            s3 = a3.f.x + a3.f.y;
#pragma unroll
            for (int off = 16; off; off >>= 1) {
                s0 += __shfl_xor_sync(0xffffffffu, s0, off);
                s1 += __shfl_xor_sync(0xffffffffu, s1, off);
                s2 += __shfl_xor_sync(0xffffffffu, s2, off);
                s3 += __shfl_xor_sync(0xffffffffu, s3, off);
            }
        }

        // gates in parallel on lane 0 of EACH warp; pack into smem
        if (lane == 0) {
            float zi = s0 + xzi;
            float zf = s1 + xzf;
            float zg = s2 + xzg;
            float zo = s3 + xzo;
            float ig = fast_sigmoid(zi);
            float fg = fast_sigmoid(zf);
            float gg = fast_tanh(zg);
            float og = fast_sigmoid(zo);
            c_state  = fg * c_state + ig * gg;
            float h  = og * fast_tanh(c_state);
            sh_pk[wid] =
                ((unsigned long long)(exp_tag + 1u) << 32) |
                (unsigned long long)__float_as_uint(h);
            __stcg(&g_hall[(size_t)t * H_DIM + unit], h);  // consumed next launch
        }
        __syncthreads();                                   // (C)

        // batched publish: warp r (r<4) lane u stores unit u to replica r
        // -> 4 parallel coalesced 64B waves, one per replica.
        if (wid < NREP && lane < UNITS) {
            st_relaxed64(&g_pub[t & 1][wid][ubase + lane], sh_pk[lane]);
        }
        // smem hazards: sh_h overwrite at t+1 is after each thread's own poll,
        // which it reaches only after passing (C)@t -> no racing reader of
        // sh_h@t remains (all dot reads precede (C)@t). sh_pk overwrite at
        // t+1 is post-(B)@t+1; publish reads of sh_pk@t precede (B)@t+1.
    }
}

// ---------------- final FC: out[t][o] = hall[t] . fcW[o] + fcb[o] ----------
__global__ void fc_kernel(const float* __restrict__ W,
                          const float* __restrict__ b,
                          float* __restrict__ out) {
    int t    = blockIdx.x;
    int o    = threadIdx.x >> 5;   // 10 warps
    int lane = threadIdx.x & 31;
    const float4* h = (const float4*)(g_hall + (size_t)t * H_DIM);
    const float4* w = (const float4*)(W + (size_t)o * H_DIM);
    float s = 0.f;
#pragma unroll
    for (int c = 0; c < 8; c++) {
        float4 hv = h[c * 32 + lane];
        float4 wv = w[c * 32 + lane];
        s += hv.x * wv.x + hv.y * wv.y + hv.z * wv.z + hv.w * wv.w;
    }
#pragma unroll
    for (int off = 16; off; off >>= 1)
        s += __shfl_xor_sync(0xffffffffu, s, off);
    if (lane == 0) out[t * 10 + o] = s + b[o];
}

// ---------------- launch ----------------------------------------------------
extern "C" void kernel_launch(void* const* d_in, const int* in_sizes, int n_in,
                              void* d_out, int out_size) {
    const float* x     = (const float*)d_in[0];
    const float* Wih0  = (const float*)d_in[1];
    const float* Whh0  = (const float*)d_in[2];
    const float* b0    = (const float*)d_in[3];
    const float* WihR  = (const float*)d_in[4];
    const float* WhhR  = (const float*)d_in[5];
    const float* bR    = (const float*)d_in[6];
    const float* fcW   = (const float*)d_in[7];
    const float* fcb   = (const float*)d_in[8];
    float*       out   = (float*)d_out;

    dim3 ggrid(G4H / 128, T_LEN / 128);
    dim3 gblk(256);

    // layer 0
    gemm_xz<IN_DIM><<<ggrid, gblk>>>(x, Wih0, b0);
    lstm_scan<<<NCTA, 256>>>(Whh0, 0);

    // layers 1..3
    for (int l = 1; l < 4; l++) {
        const float* Wih = WihR + (size_t)(l - 1) * G4H * H_DIM;
        const float* Whh = WhhR + (size_t)(l - 1) * G4H * H_DIM;
        const float* bb  = bR   + (size_t)(l - 1) * G4H;
        gemm_xz<H_DIM><<<ggrid, gblk>>>(nullptr /* = g_hall */, Wih, bb);
        lstm_scan<<<NCTA, 256>>>(Whh, l);
    }

    fc_kernel<<<T_LEN, 320>>>(fcW, fcb, out);
}